// round 16
// baseline (speedup 1.0000x reference)
#include <cuda_runtime.h>
#include <cuda_fp16.h>
#include <cstdint>

// Shapes (fixed by the problem)
#define B_ 64
#define S_ 197
#define D_ 768
#define P_ 196
#define M_ (B_ * S_)   // 12608 = 64 * 197

#define IN_BASE 6400   // rows >= IN_BASE gathered inline by the GEMM kernel
#define NCTA    296    // 2 CTAs/SM * 148 SMs — all co-resident

// Device scratch (no cudaMalloc allowed)
__device__ __half g_xs[(size_t)M_ * D_];    // weighted-gathered x, fp16
__device__ __half g_wt[(size_t)D_ * D_];    // Wv^T in fp16: g_wt[n][k]
__device__ float  g_ws[M_];                 // per-row weight sum
__device__ int    g_cnt[49];                // ready counters for blocks 50..98

__device__ __forceinline__ uint32_t smem_u32(const void* p) {
    uint32_t a;
    asm("{ .reg .u64 t; cvta.to.shared.u64 t, %1; cvt.u32.u64 %0, t; }"
        : "=r"(a) : "l"(p));
    return a;
}
__device__ __forceinline__ void cp_async16(uint32_t dst, const void* src) {
    asm volatile("cp.async.cg.shared.global [%0], [%1], 16;"
                 :: "r"(dst), "l"(src));
}
#define CP_COMMIT() asm volatile("cp.async.commit_group;" ::: "memory")
#define CP_WAIT(n)  asm volatile("cp.async.wait_group %0;" :: "n"(n) : "memory")

__device__ __forceinline__ void ldsm_x4(uint32_t* r, uint32_t addr) {
    asm volatile("ldmatrix.sync.aligned.m8n8.x4.shared.b16 {%0,%1,%2,%3}, [%4];"
                 : "=r"(r[0]), "=r"(r[1]), "=r"(r[2]), "=r"(r[3]) : "r"(addr));
}
__device__ __forceinline__ void mma_f16(float* d, const uint32_t* a, const uint32_t* b)
{
    asm volatile(
        "mma.sync.aligned.m16n8k16.row.col.f32.f16.f16.f32 "
        "{%0,%1,%2,%3}, {%4,%5,%6,%7}, {%8,%9}, {%0,%1,%2,%3};"
        : "+f"(d[0]), "+f"(d[1]), "+f"(d[2]), "+f"(d[3])
        : "r"(a[0]), "r"(a[1]), "r"(a[2]), "r"(a[3]), "r"(b[0]), "r"(b[1]));
}

__device__ __forceinline__ int wrap197(int i)
{
    int r = i % S_;
    return (r < 0) ? r + S_ : r;
}

// Shared scalar-prelude for one output row (s >= 1). Returns idx/w; writes wsum.
__device__ __forceinline__ void row_scalars(
    int b, int p, const int* img_ids, const float* avgs, const float* stds,
    const float* noise, int4* idx_out, float4* w_out, float* wsum_out)
{
    const int id = img_ids[b];
    const float nx = noise[(size_t)(b * 2 + 0) * P_ + p];
    const float ny = noise[(size_t)(b * 2 + 1) * P_ + p];
    const size_t gb = (size_t)id * 2 * P_;
    const float ax = avgs[gb + p],  ay = avgs[gb + P_ + p];
    const float sx = stds[gb + p],  sy = stds[gb + P_ + p];
    const float kx = (nx - ax) / sx;
    const float ky = (ny - ay) / sy;
    const float x1 = ceilf(kx),  x2 = floorf(kx);
    const float y1 = ceilf(ky),  y2 = floorf(ky);
    const float wx1 = 1.0f - fabsf(x1 - kx);
    const float wx2 = 1.0f - fabsf(x2 - kx);
    const float wy1 = 1.0f - fabsf(y1 - ky);
    const float wy2 = 1.0f - fabsf(y2 - ky);
    const float w11 = wx1 * wy1, w21 = wx2 * wy1;
    const float w12 = wx1 * wy2, w22 = wx2 * wy2;
    *w_out   = make_float4(w11, w21, w12, w22);
    *idx_out = make_int4(wrap197((int)(14.0f * y1 + x1)),
                         wrap197((int)(14.0f * y1 + x2)),
                         wrap197((int)(14.0f * y2 + x1)),
                         wrap197((int)(14.0f * y2 + x2)));
    *wsum_out = w11 + w21 + w12 + w22;
}

// ---------------------------------------------------------------------------
// reset: zero the block-ready counters (runs first every replay)
// ---------------------------------------------------------------------------
__global__ void reset_kernel()
{
    if (threadIdx.x < 49) g_cnt[threadIdx.x] = 0;
}

// ---------------------------------------------------------------------------
// prep: blocks [0, IN_BASE) gather rows 0..6399 -> xs + wsum; blocks
// [IN_BASE, IN_BASE+576) transpose+convert Wv -> Wt[n][k] fp16.
// Rows >= 6400 are gathered inline by the GEMM kernel (overlapped).
// ---------------------------------------------------------------------------
__global__ __launch_bounds__(192) void prep_kernel(
    const float* __restrict__ x, const int* __restrict__ img_ids,
    const float* __restrict__ avgs, const float* __restrict__ stds,
    const float* __restrict__ noise, const float* __restrict__ W,
    __half* __restrict__ xs, __half* __restrict__ wt, float* __restrict__ wsum)
{
    __shared__ float tile[32][33];
    __shared__ int4   s_idx;
    __shared__ float4 s_w;
    const int bid = blockIdx.x;
    const int tid = threadIdx.x;

    if (bid >= IN_BASE) {
        // ---- transpose tile of W ----
        const int t  = bid - IN_BASE;   // 0..575
        const int tx = t % 24;
        const int ty = t / 24;
        const int lx = tid & 31;
        const int ly = tid >> 5;        // 0..5
#pragma unroll
        for (int i = 0; i < 36; i += 6) {
            const int r = ly + i;
            if (r < 32)
                tile[r][lx] = W[(size_t)(ty * 32 + r) * D_ + tx * 32 + lx];
        }
        __syncthreads();
#pragma unroll
        for (int i = 0; i < 36; i += 6) {
            const int r = ly + i;
            if (r < 32)
                wt[(size_t)(tx * 32 + r) * D_ + ty * 32 + lx] =
                    __float2half_rn(tile[lx][r]);
        }
        return;
    }

    // ---- gather row (row = bid < 6400) ----
    const int row = bid;
    const int b = row / S_;
    const int s = row - b * S_;
    const int t = tid;                  // 0..191, 4 elements each

    uint2* orow = (uint2*)(xs + (size_t)row * D_) + t;
    if (s == 0) {
        *orow = make_uint2(0u, 0u);
        if (t == 0) wsum[row] = 0.0f;
        return;
    }

    if (tid == 0) {
        float wsv;
        row_scalars(b, s - 1, img_ids, avgs, stds, noise, (int4*)&s_idx,
                    (float4*)&s_w, &wsv);
        wsum[row] = wsv;
    }
    __syncthreads();

    const int4   id = s_idx;
    const float4 w  = s_w;
    const float4* xb = (const float4*)x + (size_t)b * S_ * (D_ / 4);
    const float4 a = xb[(size_t)id.x * (D_ / 4) + t];
    const float4 c = xb[(size_t)id.y * (D_ / 4) + t];
    const float4 d = xb[(size_t)id.z * (D_ / 4) + t];
    const float4 e = xb[(size_t)id.w * (D_ / 4) + t];

    float4 r;
    r.x = w.x * a.x + w.y * c.x + w.z * d.x + w.w * e.x;
    r.y = w.x * a.y + w.y * c.y + w.z * d.y + w.w * e.y;
    r.z = w.x * a.z + w.y * c.z + w.z * d.z + w.w * e.z;
    r.w = w.x * a.w + w.y * c.w + w.z * d.w + w.w * e.w;

    __half2 h0 = __floats2half2_rn(r.x, r.y);
    __half2 h1 = __floats2half2_rn(r.z, r.w);
    uint2 o;
    o.x = *(uint32_t*)&h0;
    o.y = *(uint32_t*)&h1;
    *orow = o;
}

// ---------------------------------------------------------------------------
// FP16 tensor GEMM (R11 body) + INLINE GATHER of rows >= 6400.
// Grid = 296 (all co-resident). Each CTA: computes scalars for its 20-21
// rows, drains 4 gather chunk-tasks/thread per stage of tile 1 (tile 1
// always has m <= 49 -> never waits on inline data), fences, flags block
// counters; tiles with m >= 50 (second tile, ~20us in) spin on the flags.
// ---------------------------------------------------------------------------
#define BK     64
#define NSTG   12          // 768/64
#define STAGES 3
#define A_TILE 16384
#define STAGE_B (2 * A_TILE)               // 32768
#define GEMM_SMEM (STAGES * STAGE_B)       // 98304
#define SMEM_TOTAL (GEMM_SMEM + 1024)      // + gather scalar scratch
#define NTILES 594
#define TPS    4           // gather tasks per thread per stage

__global__ __launch_bounds__(128) void gemm_f16(
    const __half* __restrict__ A, const __half* __restrict__ Bt,
    const float* __restrict__ bias, float* __restrict__ wsum,
    float* __restrict__ C,
    const float* __restrict__ x, const int* __restrict__ img_ids,
    const float* __restrict__ avgs, const float* __restrict__ stds,
    const float* __restrict__ noise, __half* __restrict__ xs_out)
{
    extern __shared__ char smem[];
    const uint32_t sb = smem_u32(smem);

    const int bid  = blockIdx.x;
    const int tid  = threadIdx.x;      // 0..127
    const int wid  = tid >> 5;
    const int lane = tid & 31;
    const int g    = lane >> 2;
    const int t4   = lane & 3;
    const int wm   = wid & 1;
    const int wn   = wid >> 1;

    const int row0 = tid >> 3;
    const int cch  = tid & 7;
    const uint32_t dst0 =
        (uint32_t)(row0 * 128 + ((cch ^ (row0 & 7)) << 4));

    const int aRowL = wm * 64 + ((lane >> 3) & 1) * 8 + (lane & 7);
    const int aHi   = lane >> 4;
    const int bRowL = wn * 64 + (lane >> 4) * 8 + (lane & 7);
    const int bHi   = (lane >> 3) & 1;

    uint32_t aBase[4], bBase[4];
    int aSel[4], bSel[4];
#pragma unroll
    for (int f = 0; f < 4; f++) {
        const int ar = aRowL + f * 16;
        const int br = bRowL + f * 16;
        aBase[f] = (uint32_t)(ar * 128);
        bBase[f] = (uint32_t)(br * 128);
        aSel[f]  = ar & 7;
        bSel[f]  = br & 7;
    }

    // ---- inline-gather setup: this CTA's rows g = IN_BASE + bid + 296k ----
    int4*   sIdxG = (int4*)(smem + GEMM_SMEM);          // 24 * 16
    float4* sWG   = (float4*)(smem + GEMM_SMEM + 384);  // 24 * 16
    int*    sOffG = (int*)(smem + GEMM_SMEM + 768);     // 24 * 4
    const int nr = (bid <= 287) ? 21 : 20;
    if (tid < nr) {
        const int gr = IN_BASE + bid + 296 * tid;
        const int bb = gr / S_;
        const int ss = gr - bb * S_;
        sOffG[tid] = bb * S_ * (D_ / 4);
        if (ss == 0) {
            sIdxG[tid] = make_int4(-1, 0, 0, 0);
            wsum[gr] = 0.0f;
        } else {
            int4 idv; float4 wv; float wsv;
            row_scalars(bb, ss - 1, img_ids, avgs, stds, noise, &idv, &wv, &wsv);
            sIdxG[tid] = idv;
            sWG[tid]   = wv;
            wsum[gr]   = wsv;
        }
    }
    __syncthreads();
    const int ptasks = (nr * 192 + 127) / 128;   // per-thread task count (30/32)
    int pc = 0;                                  // tasks processed (uniform)
    int flagged = 0;

    for (int tile = bid; tile < NTILES; tile += NCTA) {
        const int m0t = tile / 6;
        const int m0 = m0t * 128;
        const int n0 = (tile % 6) * 128;

        // wait for inline-gathered A block (only ever on 2nd/3rd tile)
        if (m0t >= 50) {
            if (tid == 0) {
                const int need = (m0t == 98) ? 64 : 128;
                volatile int* cp = &g_cnt[m0t - 50];
                while (*cp < need) __nanosleep(128);
            }
            __syncthreads();
        }

        int aOff[8];
#pragma unroll
        for (int i = 0; i < 8; i++) {
            int ga = m0 + row0 + 16 * i;
            if (ga >= M_) ga = M_ - 1;
            aOff[i] = ga * D_ + cch * 8;
        }
        const int bOff0 = (n0 + row0) * D_ + cch * 8;

        float acc[4][8][4];
#pragma unroll
        for (int i = 0; i < 4; i++)
#pragma unroll
            for (int j = 0; j < 8; j++)
#pragma unroll
                for (int r = 0; r < 4; r++) acc[i][j][r] = 0.0f;

        // prologue: stages 0,1
#pragma unroll
        for (int s = 0; s < STAGES - 1; s++) {
            const int k0 = s * BK;
            const uint32_t so = (uint32_t)(s * STAGE_B) + dst0;
#pragma unroll
            for (int i = 0; i < 8; i++) {
                cp_async16(sb + so + i * 2048,          A  + aOff[i] + k0);
                cp_async16(sb + so + A_TILE + i * 2048, Bt + bOff0 + i * (16 * D_) + k0);
            }
            CP_COMMIT();
        }

        uint32_t a[2][4][4], bb[2][4][4];
        int slot = 0, pslot = 2;
        for (int s = 0; s < NSTG; s++) {
            CP_WAIT(1);
            __syncthreads();

            const uint32_t AbO = sb + (uint32_t)(slot * STAGE_B);
            const uint32_t BbO = AbO + A_TILE;

#pragma unroll
            for (int f = 0; f < 4; f++) {
                ldsm_x4(a[0][f],  AbO + aBase[f] + ((aHi ^ aSel[f]) << 4));
                ldsm_x4(bb[0][f], BbO + bBase[f] + ((bHi ^ bSel[f]) << 4));
            }

            const int sl = s + STAGES - 1;
            if (sl < NSTG) {
                const int k0 = sl * BK;
                const uint32_t so = (uint32_t)(pslot * STAGE_B) + dst0;
#pragma unroll
                for (int i = 0; i < 8; i++) {
                    cp_async16(sb + so + i * 2048,          A  + aOff[i] + k0);
                    cp_async16(sb + so + A_TILE + i * 2048, Bt + bOff0 + i * (16 * D_) + k0);
                }
            }
            CP_COMMIT();

            // ---- inline gather: TPS chunk-tasks per thread per stage ----
            if (pc < ptasks) {
#pragma unroll
                for (int i = 0; i < TPS; i++) {
                    const int t = (pc + i) * 128 + tid;
                    const int r = t / 192;
                    if (r < nr) {
                        const int c = t - r * 192;
                        const int gr = IN_BASE + bid + 296 * r;
                        uint2* orow = (uint2*)(xs_out + (size_t)gr * D_) + c;
                        const int4 idv = sIdxG[r];
                        if (idv.x < 0) {
                            *orow = make_uint2(0u, 0u);
                        } else {
                            const float4* xb = (const float4*)x + sOffG[r];
                            const float4 w = sWG[r];
                            const float4 va = xb[(size_t)idv.x * 192 + c];
                            const float4 vb = xb[(size_t)idv.y * 192 + c];
                            const float4 vc = xb[(size_t)idv.z * 192 + c];
                            const float4 vd = xb[(size_t)idv.w * 192 + c];
                            float4 rr;
                            rr.x = w.x * va.x + w.y * vb.x + w.z * vc.x + w.w * vd.x;
                            rr.y = w.x * va.y + w.y * vb.y + w.z * vc.y + w.w * vd.y;
                            rr.z = w.x * va.z + w.y * vb.z + w.z * vc.z + w.w * vd.z;
                            rr.w = w.x * va.w + w.y * vb.w + w.z * vc.w + w.w * vd.w;
                            __half2 h0 = __floats2half2_rn(rr.x, rr.y);
                            __half2 h1 = __floats2half2_rn(rr.z, rr.w);
                            uint2 o;
                            o.x = *(uint32_t*)&h0;
                            o.y = *(uint32_t*)&h1;
                            *orow = o;
                        }
                    }
                }
                pc += TPS;
                if (pc >= ptasks) __threadfence();   // my stores drained
            } else if (!flagged) {
                // previous stage ended with every thread's fence; this
                // stage's top __syncthreads ordered them before us.
                if (tid == 0) {
                    for (int r = 0; r < nr; r++) {
                        const int blk = (IN_BASE + bid + 296 * r) >> 7;
                        atomicAdd(&g_cnt[blk - 50], 1);
                    }
                }
                flagged = 1;
            }

#pragma unroll
            for (int ks = 0; ks < 4; ks++) {
                const int cur = ks & 1;
                const int nxt = cur ^ 1;
                if (ks < 3) {
                    const int kc = 2 * (ks + 1);
#pragma unroll
                    for (int f = 0; f < 4; f++) {
                        ldsm_x4(a[nxt][f],  AbO + aBase[f] + (((kc + aHi) ^ aSel[f]) << 4));
                        ldsm_x4(bb[nxt][f], BbO + bBase[f] + (((kc + bHi) ^ bSel[f]) << 4));
                    }
                }
#pragma unroll
                for (int fm = 0; fm < 4; fm++) {
#pragma unroll
                    for (int fnp = 0; fnp < 4; fnp++) {
                        mma_f16(acc[fm][2 * fnp],     a[cur][fm], &bb[cur][fnp][0]);
                        mma_f16(acc[fm][2 * fnp + 1], a[cur][fm], &bb[cur][fnp][2]);
                    }
                }
            }
            slot  = (slot == 2)  ? 0 : slot + 1;
            pslot = (pslot == 2) ? 0 : pslot + 1;
        }

        // epilogue: out = acc + wsum[row]*bias[col]; class-token rows = 1.0
#pragma unroll
        for (int fm = 0; fm < 4; fm++) {
            const int row0e = m0 + wm * 64 + fm * 16 + g;
            const int row1e = row0e + 8;
            const bool ok0 = row0e < M_;
            const bool ok1 = row1e < M_;
            const bool cls0 = (row0e % S_) == 0;
            const bool cls1 = (row1e % S_) == 0;
            const float ws0 = ok0 ? wsum[row0e] : 0.0f;
            const float ws1 = ok1 ? wsum[row1e] : 0.0f;
#pragma unroll
            for (int fn = 0; fn < 8; fn++) {
                const int col = n0 + wn * 64 + fn * 8 + t4 * 2;
                const float b0 = bias[col];
                const float b1 = bias[col + 1];
                if (ok0) {
                    float2 o;
                    o.x = cls0 ? 1.0f : acc[fm][fn][0] + ws0 * b0;
                    o.y = cls0 ? 1.0f : acc[fm][fn][1] + ws0 * b1;
                    *(float2*)(C + (size_t)row0e * D_ + col) = o;
                }
                if (ok1) {
                    float2 o;
                    o.x = cls1 ? 1.0f : acc[fm][fn][2] + ws1 * b0;
                    o.y = cls1 ? 1.0f : acc[fm][fn][3] + ws1 * b1;
                    *(float2*)(C + (size_t)row1e * D_ + col) = o;
                }
            }
        }
        __syncthreads();   // smem reuse guard before next persistent tile
    }
}

// ---------------------------------------------------------------------------
// Inputs (metadata order): 0:x 1:img_ids 2:mask 3:Wq 4:bq 5:Wk 6:bk
//                          7:Wv 8:bv 9:avgs 10:std_devs 11:noise
// q/k/softmax are dead (softmax over singleton axis == 1): out = sampled v,
// and sampling commutes with the linear map -> gather x first, then one GEMM.
// ---------------------------------------------------------------------------
extern "C" void kernel_launch(void* const* d_in, const int* in_sizes, int n_in,
                              void* d_out, int out_size)
{
    const float* x       = (const float*)d_in[0];
    const int*   img_ids = (const int*)d_in[1];
    const float* Wv      = (const float*)d_in[7];
    const float* bv      = (const float*)d_in[8];
    const float* avgs    = (const float*)d_in[9];
    const float* stds    = (const float*)d_in[10];
    const float* noise   = (const float*)d_in[11];
    float* out = (float*)d_out;

    __half* xs = nullptr;
    __half* wt = nullptr;
    float*  ws = nullptr;
    cudaGetSymbolAddress((void**)&xs, g_xs);
    cudaGetSymbolAddress((void**)&wt, g_wt);
    cudaGetSymbolAddress((void**)&ws, g_ws);

    cudaFuncSetAttribute(gemm_f16, cudaFuncAttributeMaxDynamicSharedMemorySize,
                         SMEM_TOTAL);

    reset_kernel<<<1, 64>>>();
    prep_kernel<<<IN_BASE + 576, 192>>>(x, img_ids, avgs, stds, noise, Wv,
                                        xs, wt, ws);
    gemm_f16<<<NCTA, 128, SMEM_TOTAL>>>(xs, wt, bv, ws, out,
                                        x, img_ids, avgs, stds, noise, xs);
}